// round 1
// baseline (speedup 1.0000x reference)
#include <cuda_runtime.h>
#include <cuda_bf16.h>
#include <cstdint>

// Problem constants
#define Bb 32
#define Nn 1024
#define Ff 3
#define Tt 32
#define Kk 3
#define Cc 64      // C_chev
#define Ct 64      // C_time
#define KM (Kk*Nn)          // 3072 reduction length
#define COLS (Cc*Tt)        // 2048 (o,t) columns

// Scratch (device globals: allocation-free per harness rules)
__device__ float gZ[(size_t)Bb * KM * COLS];    // 805 MB
__device__ float gS[(size_t)Bb * Nn * COLS];    // 268 MB

// ---------------------------------------------------------------------------
// Kernel 1: Z[b, k*1024+m, o*32+t] = sum_f x[b,m,f,t] * theta[k,f,o]
// grid (1024, 32) block 256
// ---------------------------------------------------------------------------
__global__ __launch_bounds__(256) void prep_kernel(
    const float* __restrict__ x, const float* __restrict__ theta)
{
    const int m = blockIdx.x;
    const int b = blockIdx.y;
    __shared__ float th[Kk * Ff * Cc];   // 576
    __shared__ float xs[Ff * Tt];        // 96

    const int tid = threadIdx.x;
    for (int i = tid; i < Kk * Ff * Cc; i += 256) th[i] = theta[i];
    if (tid < Ff * Tt)
        xs[tid] = x[((size_t)(b * Nn + m) * Ff) * Tt + tid];
    __syncthreads();

    float* Zb = gZ + (size_t)b * KM * COLS;
    #pragma unroll
    for (int i = 0; i < 24; ++i) {
        int idx = tid + i * 256;           // 0..6143 over (k,o,t)
        int k   = idx >> 11;               // /2048
        int rem = idx & 2047;
        int o   = rem >> 5;
        int t   = rem & 31;
        float v = xs[0 * Tt + t] * th[(k * Ff + 0) * Cc + o]
                + xs[1 * Tt + t] * th[(k * Ff + 1) * Cc + o]
                + xs[2 * Tt + t] * th[(k * Ff + 2) * Cc + o];
        Zb[(size_t)(k * Nn + m) * COLS + rem] = v;
    }
}

// ---------------------------------------------------------------------------
// Kernel 2: batched SGEMM  S[b, n, col] = relu( sum_km cheb[km, n] * Z[b, km, col] )
// cheb row-major (3072 x 1024), Z row-major (3072 x 2048) per batch.
// Tile 128x128, BK=8, 256 threads, 8x8 per thread via packed fma.rn.f32x2.
// grid (16 colTiles, 8 nTiles, 32 b)
// ---------------------------------------------------------------------------
#define BK 8
__global__ __launch_bounds__(256) void gemm_kernel(const float* __restrict__ A /*cheb*/)
{
    const int ct0 = blockIdx.x * 128;
    const int nt0 = blockIdx.y * 128;
    const int b   = blockIdx.z;
    const float* __restrict__ Bp = gZ + (size_t)b * KM * COLS;
    float* __restrict__ Cp       = gS + (size_t)b * Nn * COLS;

    __shared__ float As[2][BK][128];
    __shared__ float Bs[2][BK][128];

    const int tid = threadIdx.x;
    const int lr  = tid >> 5;          // 0..7 (k row within tile)
    const int lc  = (tid & 31) << 2;   // 0..124 (col within tile)
    const int tx  = tid & 15;          // col group
    const int ty  = tid >> 4;          // row group

    unsigned long long c2[8][4];
    #pragma unroll
    for (int i = 0; i < 8; ++i)
        #pragma unroll
        for (int j = 0; j < 4; ++j) c2[i][j] = 0ULL;

    // prologue: tile 0
    float4 pa = *(const float4*)(A  + (size_t)lr * Nn   + nt0 + lc);
    float4 pb = *(const float4*)(Bp + (size_t)lr * COLS + ct0 + lc);
    *(float4*)&As[0][lr][lc] = pa;
    *(float4*)&Bs[0][lr][lc] = pb;
    __syncthreads();

    const int NT = KM / BK;  // 384
    for (int kt = 0; kt < NT; ++kt) {
        const int cur = kt & 1;
        const int nxt = cur ^ 1;
        if (kt + 1 < NT) {
            const int row = (kt + 1) * BK + lr;
            pa = *(const float4*)(A  + (size_t)row * Nn   + nt0 + lc);
            pb = *(const float4*)(Bp + (size_t)row * COLS + ct0 + lc);
        }
        #pragma unroll
        for (int kk = 0; kk < BK; ++kk) {
            float4 a0 = *(const float4*)&As[cur][kk][ty * 8];
            float4 a1 = *(const float4*)&As[cur][kk][ty * 8 + 4];
            const ulonglong2* bp2 = (const ulonglong2*)&Bs[cur][kk][tx * 8];
            ulonglong2 b01 = bp2[0];
            ulonglong2 b23 = bp2[1];
            unsigned long long bv[4] = {b01.x, b01.y, b23.x, b23.y};
            float av[8] = {a0.x, a0.y, a0.z, a0.w, a1.x, a1.y, a1.z, a1.w};
            #pragma unroll
            for (int i = 0; i < 8; ++i) {
                unsigned long long a2;
                asm("mov.b64 %0, {%1, %1};" : "=l"(a2) : "f"(av[i]));
                #pragma unroll
                for (int j = 0; j < 4; ++j)
                    asm("fma.rn.f32x2 %0, %1, %2, %0;"
                        : "+l"(c2[i][j]) : "l"(a2), "l"(bv[j]));
            }
        }
        if (kt + 1 < NT) {
            *(float4*)&As[nxt][lr][lc] = pa;
            *(float4*)&Bs[nxt][lr][lc] = pb;
            __syncthreads();
        }
    }

    // epilogue: unpack, relu, store
    #pragma unroll
    for (int i = 0; i < 8; ++i) {
        const int row = nt0 + ty * 8 + i;
        float v[8];
        #pragma unroll
        for (int j = 0; j < 4; ++j) {
            float lo, hi;
            asm("mov.b64 {%0, %1}, %2;" : "=f"(lo), "=f"(hi) : "l"(c2[i][j]));
            v[2 * j]     = fmaxf(lo, 0.f);
            v[2 * j + 1] = fmaxf(hi, 0.f);
        }
        float4* dst = (float4*)(Cp + (size_t)row * COLS + ct0 + tx * 8);
        dst[0] = make_float4(v[0], v[1], v[2], v[3]);
        dst[1] = make_float4(v[4], v[5], v[6], v[7]);
    }
}

// ---------------------------------------------------------------------------
// Kernel 3: per (b,n): time conv (1x3 over t, 64->64 ch) + residual 1x1 conv
//           + relu + LayerNorm over channel + transposed store out[b,n,c,t].
// grid (1024, 32) block 256, dynamic smem.
// ---------------------------------------------------------------------------
// smem layout (floats):
//   wt  [3][64][64]   12288   (w_time reorganized tap-major)
//   Sp  [64][36]       2304   (relu'd spatial, t padded: index t+1, zeros at 0 and 33)
//   po  [64][33]       2112   (pre-LN activations)
//   xs  [3][32]          96
//   wr  [64][3]         192
//   bt,br,gm,bb [64]x4  256
//   mu,rs [32]x2         64
#define EPI_WT   0
#define EPI_SP   12288
#define EPI_PO   (EPI_SP + 64 * 36)
#define EPI_XS   (EPI_PO + 64 * 33)
#define EPI_WR   (EPI_XS + 96)
#define EPI_BT   (EPI_WR + 192)
#define EPI_BR   (EPI_BT + 64)
#define EPI_GM   (EPI_BR + 64)
#define EPI_BB   (EPI_GM + 64)
#define EPI_MU   (EPI_BB + 64)
#define EPI_RS   (EPI_MU + 32)
#define EPI_FLOATS (EPI_RS + 32)
#define EPI_SMEM_BYTES (EPI_FLOATS * 4)

__global__ __launch_bounds__(256) void epi_kernel(
    const float* __restrict__ x,
    const float* __restrict__ w_time, const float* __restrict__ b_time,
    const float* __restrict__ w_res,  const float* __restrict__ b_res,
    const float* __restrict__ gamma,  const float* __restrict__ beta,
    float* __restrict__ out)
{
    extern __shared__ float sm[];
    const int n = blockIdx.x;
    const int b = blockIdx.y;
    const int tid = threadIdx.x;

    // --- loads ---
    // w_time source layout (c, ci, tap) -> smem [tap][c][ci]
    for (int i = tid; i < Ct * Cc * 3; i += 256) {
        int c   = i / (Cc * 3);
        int r   = i - c * (Cc * 3);
        int ci  = r / 3;
        int tap = r - ci * 3;
        sm[EPI_WT + tap * (Ct * Cc) + c * Cc + ci] = w_time[i];
    }
    // zero the padded Sp
    for (int i = tid; i < 64 * 36; i += 256) sm[EPI_SP + i] = 0.f;
    if (tid < Ff * Tt) sm[EPI_XS + tid] = x[((size_t)(b * Nn + n) * Ff) * Tt + tid];
    if (tid < Ct * Ff) sm[EPI_WR + tid] = w_res[tid];
    if (tid < Ct) {
        sm[EPI_BT + tid] = b_time[tid];
        sm[EPI_BR + tid] = b_res[tid];
        sm[EPI_GM + tid] = gamma[tid];
        sm[EPI_BB + tid] = beta[tid];
    }
    __syncthreads();
    // load relu'd spatial slice: S[b,n,o,t] -> Sp[o][t+1]
    const float* Sslice = gS + (size_t)(b * Nn + n) * COLS;
    for (int i = tid; i < COLS; i += 256) {
        int o = i >> 5, t = i & 31;
        sm[EPI_SP + o * 36 + t + 1] = Sslice[i];
    }
    __syncthreads();

    // --- time conv + residual + relu ---
    const int c     = tid >> 2;        // 0..63
    const int tg    = tid & 3;
    const int tbase = tg * 8;          // t block of 8

    float acc[8];
    #pragma unroll
    for (int j = 0; j < 8; ++j) acc[j] = 0.f;

    for (int ci = 0; ci < Cc; ++ci) {
        const float* row = &sm[EPI_SP + ci * 36 + tbase];  // covers t-1 .. t+8 (padded)
        float4 s0 = *(const float4*)(row);
        float4 s1 = *(const float4*)(row + 4);
        float2 s2 = *(const float2*)(row + 8);
        float s[10] = {s0.x, s0.y, s0.z, s0.w, s1.x, s1.y, s1.z, s1.w, s2.x, s2.y};
        float w0 = sm[EPI_WT + 0 * (Ct * Cc) + c * Cc + ci];
        float w1 = sm[EPI_WT + 1 * (Ct * Cc) + c * Cc + ci];
        float w2 = sm[EPI_WT + 2 * (Ct * Cc) + c * Cc + ci];
        #pragma unroll
        for (int j = 0; j < 8; ++j)
            acc[j] += w0 * s[j] + w1 * s[j + 1] + w2 * s[j + 2];
    }
    const float wr0 = sm[EPI_WR + c * 3 + 0];
    const float wr1 = sm[EPI_WR + c * 3 + 1];
    const float wr2 = sm[EPI_WR + c * 3 + 2];
    const float bias = sm[EPI_BT + c] + sm[EPI_BR + c];
    #pragma unroll
    for (int j = 0; j < 8; ++j) {
        int t = tbase + j;
        float res = wr0 * sm[EPI_XS + 0 * Tt + t]
                  + wr1 * sm[EPI_XS + 1 * Tt + t]
                  + wr2 * sm[EPI_XS + 2 * Tt + t];
        float v = acc[j] + res + bias;
        sm[EPI_PO + c * 33 + t] = fmaxf(v, 0.f);
    }
    __syncthreads();

    // --- LayerNorm stats over channel for each t ---
    {
        const int t = tid >> 3;        // 0..31
        const int s = tid & 7;         // 8 threads per t
        float sum = 0.f, sq = 0.f;
        #pragma unroll
        for (int q = 0; q < 8; ++q) {
            float v = sm[EPI_PO + (s * 8 + q) * 33 + t];
            sum += v; sq += v * v;
        }
        #pragma unroll
        for (int off = 4; off; off >>= 1) {
            sum += __shfl_xor_sync(0xffffffffu, sum, off);
            sq  += __shfl_xor_sync(0xffffffffu, sq,  off);
        }
        if (s == 0) {
            float m   = sum * (1.f / Ct);
            float var = sq * (1.f / Ct) - m * m;
            sm[EPI_MU + t] = m;
            sm[EPI_RS + t] = rsqrtf(var + 1e-5f);
        }
    }
    __syncthreads();

    // --- normalize + transposed store out[b,n,c,t] ---
    {
        const float g = sm[EPI_GM + c];
        const float be = sm[EPI_BB + c];
        float v[8];
        #pragma unroll
        for (int j = 0; j < 8; ++j) {
            int t = tbase + j;
            v[j] = (sm[EPI_PO + c * 33 + t] - sm[EPI_MU + t]) * sm[EPI_RS + t] * g + be;
        }
        float4* dst = (float4*)(out + ((size_t)(b * Nn + n) * Ct + c) * Tt + tbase);
        dst[0] = make_float4(v[0], v[1], v[2], v[3]);
        dst[1] = make_float4(v[4], v[5], v[6], v[7]);
    }
}

// ---------------------------------------------------------------------------
extern "C" void kernel_launch(void* const* d_in, const int* in_sizes, int n_in,
                              void* d_out, int out_size)
{
    const float* x      = (const float*)d_in[0];
    const float* cheb   = (const float*)d_in[1];
    const float* theta  = (const float*)d_in[2];
    const float* w_time = (const float*)d_in[3];
    const float* b_time = (const float*)d_in[4];
    const float* w_res  = (const float*)d_in[5];
    const float* b_res  = (const float*)d_in[6];
    const float* gamma  = (const float*)d_in[7];
    const float* beta   = (const float*)d_in[8];
    float* out = (float*)d_out;

    cudaFuncSetAttribute(epi_kernel, cudaFuncAttributeMaxDynamicSharedMemorySize,
                         EPI_SMEM_BYTES);

    prep_kernel<<<dim3(Nn, Bb), 256>>>(x, theta);
    gemm_kernel<<<dim3(COLS / 128, Nn / 128, Bb), 256>>>(cheb);
    epi_kernel<<<dim3(Nn, Bb), 256, EPI_SMEM_BYTES>>>(
        x, w_time, b_time, w_res, b_res, gamma, beta, out);
}

// round 2
// speedup vs baseline: 8.3341x; 8.3341x over previous
#include <cuda_runtime.h>
#include <cuda_bf16.h>
#include <cstdint>

// Problem constants
#define Bb 32
#define Nn 1024
#define Ff 3
#define Tt 32
#define Kk 3
#define Cc 64      // C_chev
#define Ct 64      // C_time
#define FT (Ff*Tt)   // 96

// Scratch: Y[b][k][n][96] = sum_m cheb[k,m,n] * x[b,m,f,t]   (37.7 MB)
__device__ float gY[(size_t)Bb * Kk * Nn * FT];

// ---------------------------------------------------------------------------
// Kernel 1: batched GEMM over m.
//   Y[b,k,n, ft] = sum_m cheb[k*N*N + m*N + n] * x[b*N*96 + m*96 + ft]
// Tile: 128 n-rows x 96 cols, m-chunk 16, 256 threads, f32x2 packed FMA.
// grid (8 nTiles, 3 k, 32 b)
// ---------------------------------------------------------------------------
__global__ __launch_bounds__(256) void gemm1_kernel(
    const float* __restrict__ cheb, const float* __restrict__ x)
{
    const int n0 = blockIdx.x * 128;
    const int k  = blockIdx.y;
    const int b  = blockIdx.z;

    __shared__ float As[2][16][128];   // cheb tile: [m][n]
    __shared__ float Xs[2][16][96];    // x tile:    [m][ft]

    const int tid = threadIdx.x;
    const float* Abase = cheb + (size_t)k * Nn * Nn + n0;
    const float* Xbase = x + (size_t)b * Nn * FT;

    // load mapping
    const int a_r0 = tid >> 5;            // 0..7
    const int a_c  = (tid & 31) << 2;
    const int a_r1 = a_r0 + 8;            // 8..15
    const int x_r0 = tid / 24;
    const int x_c0 = (tid % 24) << 2;
    const int x_r1 = (tid + 256) / 24;    // only tid<128
    const int x_c1 = ((tid + 256) % 24) << 2;

    // compute mapping: ty rows (8), tx cols (6)
    const int ty = tid >> 4;
    const int tx = tid & 15;

    unsigned long long c2[8][3];
    #pragma unroll
    for (int i = 0; i < 8; ++i)
        #pragma unroll
        for (int j = 0; j < 3; ++j) c2[i][j] = 0ULL;

    // prologue: chunk 0
    float4 pa0 = *(const float4*)(Abase + (size_t)a_r0 * Nn + a_c);
    float4 pa1 = *(const float4*)(Abase + (size_t)a_r1 * Nn + a_c);
    float4 px0 = *(const float4*)(Xbase + (size_t)x_r0 * FT + x_c0);
    float4 px1;
    if (tid < 128) px1 = *(const float4*)(Xbase + (size_t)x_r1 * FT + x_c1);
    *(float4*)&As[0][a_r0][a_c] = pa0;
    *(float4*)&As[0][a_r1][a_c] = pa1;
    *(float4*)&Xs[0][x_r0][x_c0] = px0;
    if (tid < 128) *(float4*)&Xs[0][x_r1][x_c1] = px1;
    __syncthreads();

    const int NT = Nn / 16;   // 64 m-chunks
    for (int mt = 0; mt < NT; ++mt) {
        const int cur = mt & 1;
        const int nxt = cur ^ 1;
        if (mt + 1 < NT) {
            const int m0 = (mt + 1) * 16;
            pa0 = *(const float4*)(Abase + (size_t)(m0 + a_r0) * Nn + a_c);
            pa1 = *(const float4*)(Abase + (size_t)(m0 + a_r1) * Nn + a_c);
            px0 = *(const float4*)(Xbase + (size_t)(m0 + x_r0) * FT + x_c0);
            if (tid < 128) px1 = *(const float4*)(Xbase + (size_t)(m0 + x_r1) * FT + x_c1);
        }
        #pragma unroll
        for (int kk = 0; kk < 16; ++kk) {
            float4 a0 = *(const float4*)&As[cur][kk][ty * 8];
            float4 a1 = *(const float4*)&As[cur][kk][ty * 8 + 4];
            const unsigned long long* xp =
                (const unsigned long long*)&Xs[cur][kk][tx * 6];
            unsigned long long xv0 = xp[0], xv1 = xp[1], xv2 = xp[2];
            float av[8] = {a0.x, a0.y, a0.z, a0.w, a1.x, a1.y, a1.z, a1.w};
            #pragma unroll
            for (int i = 0; i < 8; ++i) {
                unsigned long long ad;
                asm("mov.b64 %0, {%1, %1};" : "=l"(ad) : "f"(av[i]));
                asm("fma.rn.f32x2 %0, %1, %2, %0;" : "+l"(c2[i][0]) : "l"(ad), "l"(xv0));
                asm("fma.rn.f32x2 %0, %1, %2, %0;" : "+l"(c2[i][1]) : "l"(ad), "l"(xv1));
                asm("fma.rn.f32x2 %0, %1, %2, %0;" : "+l"(c2[i][2]) : "l"(ad), "l"(xv2));
            }
        }
        if (mt + 1 < NT) {
            *(float4*)&As[nxt][a_r0][a_c] = pa0;
            *(float4*)&As[nxt][a_r1][a_c] = pa1;
            *(float4*)&Xs[nxt][x_r0][x_c0] = px0;
            if (tid < 128) *(float4*)&Xs[nxt][x_r1][x_c1] = px1;
            __syncthreads();
        }
    }

    // store Y tile
    #pragma unroll
    for (int i = 0; i < 8; ++i) {
        const int n = n0 + ty * 8 + i;
        unsigned long long* dst = (unsigned long long*)
            (gY + ((size_t)((b * Kk + k) * Nn + n)) * FT + tx * 6);
        dst[0] = c2[i][0];
        dst[1] = c2[i][1];
        dst[2] = c2[i][2];
    }
}

// ---------------------------------------------------------------------------
// Kernel 2 (fused): per (b, n-group of 8):
//   S[o,t] = relu( sum_{k,f} theta[k,f,o] * Y[b,k,n,f*32+t] )
//   conv (1x3 over t, 64->64) + residual 1x1 + relu + LayerNorm(channel)
//   store out[b,n,c,t].
// 256 threads. Conv packed over channel pairs via fma.rn.f32x2.
// ---------------------------------------------------------------------------
// smem layout (floats)
#define SB_WT   0                         // [tap][ci][c]  3*64*64
#define SB_TH   (SB_WT + 3*64*64)         // theta (k,f,o) 576
#define SB_WR   (SB_TH + 576)             // [f][c]        192
#define SB_BI   (SB_WR + 192)             // b_time+b_res  64
#define SB_GM   (SB_BI + 64)
#define SB_BB   (SB_GM + 64)
#define SB_XS   (SB_BB + 64)              // x slice 96
#define SB_YK   (SB_XS + 96)              // Y slice 3*96
#define SB_SP   (SB_YK + 288)             // padded S [ci][36]
#define SB_PO   (SB_SP + 64*36)           // pre-LN [c][33]
#define SB_MU   (SB_PO + 64*33)
#define SB_RS   (SB_MU + 32)
#define SB_FLOATS (SB_RS + 32)
#define SB_BYTES (SB_FLOATS * 4)
#define GRP 8

__global__ __launch_bounds__(256) void fused_epi_kernel(
    const float* __restrict__ x,
    const float* __restrict__ theta,
    const float* __restrict__ w_time, const float* __restrict__ b_time,
    const float* __restrict__ w_res,  const float* __restrict__ b_res,
    const float* __restrict__ gamma,  const float* __restrict__ beta,
    float* __restrict__ out)
{
    extern __shared__ float sm[];
    const int ng0 = blockIdx.x * GRP;
    const int b   = blockIdx.y;
    const int tid = threadIdx.x;

    // ---- persistent weight loads ----
    for (int i = tid; i < Ct * Cc * 3; i += 256) {
        int c   = i / (Cc * 3);
        int r   = i - c * (Cc * 3);
        int ci  = r / 3;
        int tap = r - ci * 3;
        sm[SB_WT + tap * (Cc * Ct) + ci * Ct + c] = w_time[i];
    }
    for (int i = tid; i < Kk * Ff * Cc; i += 256) sm[SB_TH + i] = theta[i];
    if (tid < Ct * Ff) {
        int c = tid / 3, f = tid - c * 3;
        sm[SB_WR + f * Ct + c] = w_res[tid];
    }
    if (tid < Ct) {
        sm[SB_BI + tid] = b_time[tid] + b_res[tid];
        sm[SB_GM + tid] = gamma[tid];
        sm[SB_BB + tid] = beta[tid];
    }
    __syncthreads();

    // thread mappings
    const int cA  = tid >> 2;          // theta stage: channel 0..63
    const int tgA = tid & 3;           // 8 t's
    const int c2i = tid >> 3;          // conv stage: channel pair 0..31
    const int tgB = tid & 7;           // 4 t's
    const int tB  = tgB * 4;

    for (int nn = 0; nn < GRP; ++nn) {
        const int n = ng0 + nn;

        // ---- per-n loads ----
        if (tid < FT)
            sm[SB_XS + tid] = x[((size_t)(b * Nn + n)) * FT + tid];
        const float* Ybase = gY + ((size_t)(b * Kk) * Nn + n) * FT;
        for (int i = tid; i < Kk * FT; i += 256) {
            int k = i / FT, ft = i - k * FT;
            sm[SB_YK + i] = Ybase[(size_t)k * Nn * FT + ft];
        }
        __syncthreads();

        // ---- theta contraction + relu -> Sp (padded t+1) ----
        {
            float sacc[8];
            #pragma unroll
            for (int j = 0; j < 8; ++j) sacc[j] = 0.f;
            #pragma unroll
            for (int k = 0; k < Kk; ++k)
                #pragma unroll
                for (int f = 0; f < Ff; ++f) {
                    float coef = sm[SB_TH + k * (Ff * Cc) + f * Cc + cA];
                    const float* yp = &sm[SB_YK + k * FT + f * Tt + tgA * 8];
                    #pragma unroll
                    for (int j = 0; j < 8; ++j) sacc[j] += coef * yp[j];
                }
            float* sp = &sm[SB_SP + cA * 36];
            #pragma unroll
            for (int j = 0; j < 8; ++j)
                sp[tgA * 8 + j + 1] = fmaxf(sacc[j], 0.f);
            if (tgA == 0) { sp[0] = 0.f; sp[33] = 0.f; }
        }
        __syncthreads();

        // ---- conv + residual (channel-pair packed) ----
        {
            unsigned long long acc2[4];
            #pragma unroll
            for (int j = 0; j < 4; ++j) acc2[j] = 0ULL;

            for (int ci = 0; ci < Cc; ++ci) {
                const unsigned long long* wp0 = (const unsigned long long*)
                    &sm[SB_WT + 0 * (Cc * Ct) + ci * Ct + 2 * c2i];
                const unsigned long long* wp1 = (const unsigned long long*)
                    &sm[SB_WT + 1 * (Cc * Ct) + ci * Ct + 2 * c2i];
                const unsigned long long* wp2 = (const unsigned long long*)
                    &sm[SB_WT + 2 * (Cc * Ct) + ci * Ct + 2 * c2i];
                unsigned long long w0 = wp0[0], w1 = wp1[0], w2 = wp2[0];

                const float* srow = &sm[SB_SP + ci * 36 + tB];  // covers t-1..t+4
                float4 s4 = *(const float4*)srow;
                float2 s2 = *(const float2*)(srow + 4);
                float s[6] = {s4.x, s4.y, s4.z, s4.w, s2.x, s2.y};
                unsigned long long d[6];
                #pragma unroll
                for (int j = 0; j < 6; ++j)
                    asm("mov.b64 %0, {%1, %1};" : "=l"(d[j]) : "f"(s[j]));
                #pragma unroll
                for (int j = 0; j < 4; ++j) {
                    asm("fma.rn.f32x2 %0, %1, %2, %0;" : "+l"(acc2[j]) : "l"(w0), "l"(d[j]));
                    asm("fma.rn.f32x2 %0, %1, %2, %0;" : "+l"(acc2[j]) : "l"(w1), "l"(d[j + 1]));
                    asm("fma.rn.f32x2 %0, %1, %2, %0;" : "+l"(acc2[j]) : "l"(w2), "l"(d[j + 2]));
                }
            }
            // residual
            #pragma unroll
            for (int f = 0; f < Ff; ++f) {
                unsigned long long wr = *(const unsigned long long*)
                    &sm[SB_WR + f * Ct + 2 * c2i];
                #pragma unroll
                for (int j = 0; j < 4; ++j) {
                    unsigned long long xd;
                    asm("mov.b64 %0, {%1, %1};" : "=l"(xd)
                        : "f"(sm[SB_XS + f * Tt + tB + j]));
                    asm("fma.rn.f32x2 %0, %1, %2, %0;" : "+l"(acc2[j]) : "l"(wr), "l"(xd));
                }
            }
            // bias + relu -> po
            const float blo = sm[SB_BI + 2 * c2i];
            const float bhi = sm[SB_BI + 2 * c2i + 1];
            float* polo = &sm[SB_PO + (2 * c2i) * 33];
            float* pohi = &sm[SB_PO + (2 * c2i + 1) * 33];
            #pragma unroll
            for (int j = 0; j < 4; ++j) {
                float lo, hi;
                asm("mov.b64 {%0, %1}, %2;" : "=f"(lo), "=f"(hi) : "l"(acc2[j]));
                polo[tB + j] = fmaxf(lo + blo, 0.f);
                pohi[tB + j] = fmaxf(hi + bhi, 0.f);
            }
        }
        __syncthreads();

        // ---- LayerNorm stats ----
        {
            const int t = tid >> 3;
            const int s = tid & 7;
            float sum = 0.f, sq = 0.f;
            #pragma unroll
            for (int q = 0; q < 8; ++q) {
                float v = sm[SB_PO + (s * 8 + q) * 33 + t];
                sum += v; sq += v * v;
            }
            #pragma unroll
            for (int off = 4; off; off >>= 1) {
                sum += __shfl_xor_sync(0xffffffffu, sum, off);
                sq  += __shfl_xor_sync(0xffffffffu, sq,  off);
            }
            if (s == 0) {
                float m   = sum * (1.f / Ct);
                float var = sq * (1.f / Ct) - m * m;
                sm[SB_MU + t] = m;
                sm[SB_RS + t] = rsqrtf(var + 1e-5f);
            }
        }
        __syncthreads();

        // ---- normalize + store ----
        {
            const int clo = 2 * c2i, chi = clo + 1;
            const float glo = sm[SB_GM + clo], blo_ = sm[SB_BB + clo];
            const float ghi = sm[SB_GM + chi], bhi_ = sm[SB_BB + chi];
            float vlo[4], vhi[4];
            #pragma unroll
            for (int j = 0; j < 4; ++j) {
                const int t = tB + j;
                const float mu = sm[SB_MU + t], rs = sm[SB_RS + t];
                vlo[j] = (sm[SB_PO + clo * 33 + t] - mu) * rs * glo + blo_;
                vhi[j] = (sm[SB_PO + chi * 33 + t] - mu) * rs * ghi + bhi_;
            }
            float* obase = out + ((size_t)(b * Nn + n)) * Ct * Tt;
            *(float4*)(obase + clo * Tt + tB) = make_float4(vlo[0], vlo[1], vlo[2], vlo[3]);
            *(float4*)(obase + chi * Tt + tB) = make_float4(vhi[0], vhi[1], vhi[2], vhi[3]);
        }
        __syncthreads();
    }
}

// ---------------------------------------------------------------------------
extern "C" void kernel_launch(void* const* d_in, const int* in_sizes, int n_in,
                              void* d_out, int out_size)
{
    const float* x      = (const float*)d_in[0];
    const float* cheb   = (const float*)d_in[1];
    const float* theta  = (const float*)d_in[2];
    const float* w_time = (const float*)d_in[3];
    const float* b_time = (const float*)d_in[4];
    const float* w_res  = (const float*)d_in[5];
    const float* b_res  = (const float*)d_in[6];
    const float* gamma  = (const float*)d_in[7];
    const float* beta   = (const float*)d_in[8];
    float* out = (float*)d_out;

    cudaFuncSetAttribute(fused_epi_kernel,
                         cudaFuncAttributeMaxDynamicSharedMemorySize, SB_BYTES);

    gemm1_kernel<<<dim3(Nn / 128, Kk, Bb), 256>>>(cheb, x);
    fused_epi_kernel<<<dim3(Nn / GRP, Bb), 256, SB_BYTES>>>(
        x, theta, w_time, b_time, w_res, b_res, gamma, beta, out);
}

// round 3
// speedup vs baseline: 8.6019x; 1.0321x over previous
#include <cuda_runtime.h>
#include <cuda_bf16.h>
#include <cstdint>

#define Bb 32
#define Nn 1024
#define Ff 3
#define Tt 32
#define Kk 3
#define Cc 64
#define Ct 64
#define FT (Ff*Tt)   // 96

// Scratch: Y[b][k][n][96] = sum_m cheb[k,m,n] * x[b,m,f,t]   (37.7 MB)
__device__ float gY[(size_t)Bb * Kk * Nn * FT];

__device__ __forceinline__ unsigned long long dup2(float v) {
    unsigned long long d;
    asm("mov.b64 %0, {%1, %1};" : "=l"(d) : "f"(v));
    return d;
}

// ---------------------------------------------------------------------------
// Kernel 1: Y[b,k,n,ft] = sum_m cheb[k,m,n] * x[b,m,ft]
// Tile 128n x 96ft, m-chunk 16, 256 threads.
// X tile stored DUPLICATED in smem ((v,v) pairs) -> inner loop has zero movs:
// accumulate over n-pairs: c2[p][j] += (a[n0],a[n1]) * (x[ft],x[ft]).
// ---------------------------------------------------------------------------
__global__ __launch_bounds__(256) void gemm1_kernel(
    const float* __restrict__ cheb, const float* __restrict__ x)
{
    const int n0 = blockIdx.x * 128;
    const int k  = blockIdx.y;
    const int b  = blockIdx.z;

    __shared__ float As[2][16][128];
    __shared__ float Xd[2][16][192];   // duplicated pairs

    const int tid = threadIdx.x;
    const float* Abase = cheb + (size_t)k * Nn * Nn + n0;
    const float* Xbase = x + (size_t)b * Nn * FT;

    const int a_r0 = tid >> 5;            // 0..7
    const int a_c  = (tid & 31) << 2;
    const int a_r1 = a_r0 + 8;
    const int x_r0 = tid / 24;
    const int x_c0 = (tid % 24) << 2;
    const int x_r1 = (tid + 256) / 24;    // tid<128 only
    const int x_c1 = ((tid + 256) % 24) << 2;

    const int ty = tid >> 4;              // 0..15 -> 8 n rows
    const int tx = tid & 15;              // 0..15 -> 6 ft cols

    unsigned long long c2[4][6];
    #pragma unroll
    for (int p = 0; p < 4; ++p)
        #pragma unroll
        for (int j = 0; j < 6; ++j) c2[p][j] = 0ULL;

    // prologue
    float4 pa0 = *(const float4*)(Abase + (size_t)a_r0 * Nn + a_c);
    float4 pa1 = *(const float4*)(Abase + (size_t)a_r1 * Nn + a_c);
    float4 px0 = *(const float4*)(Xbase + (size_t)x_r0 * FT + x_c0);
    float4 px1;
    if (tid < 128) px1 = *(const float4*)(Xbase + (size_t)x_r1 * FT + x_c1);

    {
        *(float4*)&As[0][a_r0][a_c] = pa0;
        *(float4*)&As[0][a_r1][a_c] = pa1;
        ulonglong2* d0 = (ulonglong2*)&Xd[0][x_r0][2 * x_c0];
        d0[0] = make_ulonglong2(dup2(px0.x), dup2(px0.y));
        d0[1] = make_ulonglong2(dup2(px0.z), dup2(px0.w));
        if (tid < 128) {
            ulonglong2* d1 = (ulonglong2*)&Xd[0][x_r1][2 * x_c1];
            d1[0] = make_ulonglong2(dup2(px1.x), dup2(px1.y));
            d1[1] = make_ulonglong2(dup2(px1.z), dup2(px1.w));
        }
    }
    __syncthreads();

    const int NT = Nn / 16;   // 64
    for (int mt = 0; mt < NT; ++mt) {
        const int cur = mt & 1;
        const int nxt = cur ^ 1;
        if (mt + 1 < NT) {
            const int m0 = (mt + 1) * 16;
            pa0 = *(const float4*)(Abase + (size_t)(m0 + a_r0) * Nn + a_c);
            pa1 = *(const float4*)(Abase + (size_t)(m0 + a_r1) * Nn + a_c);
            px0 = *(const float4*)(Xbase + (size_t)(m0 + x_r0) * FT + x_c0);
            if (tid < 128) px1 = *(const float4*)(Xbase + (size_t)(m0 + x_r1) * FT + x_c1);
        }
        #pragma unroll
        for (int kk = 0; kk < 16; ++kk) {
            ulonglong2 a01 = *(const ulonglong2*)&As[cur][kk][ty * 8];
            ulonglong2 a23 = *(const ulonglong2*)&As[cur][kk][ty * 8 + 4];
            const ulonglong2* xp = (const ulonglong2*)&Xd[cur][kk][tx * 12];
            ulonglong2 x01 = xp[0], x23 = xp[1], x45 = xp[2];
            unsigned long long av[4] = {a01.x, a01.y, a23.x, a23.y};
            unsigned long long xv[6] = {x01.x, x01.y, x23.x, x23.y, x45.x, x45.y};
            #pragma unroll
            for (int p = 0; p < 4; ++p)
                #pragma unroll
                for (int j = 0; j < 6; ++j)
                    asm("fma.rn.f32x2 %0, %1, %2, %0;"
                        : "+l"(c2[p][j]) : "l"(av[p]), "l"(xv[j]));
        }
        if (mt + 1 < NT) {
            *(float4*)&As[nxt][a_r0][a_c] = pa0;
            *(float4*)&As[nxt][a_r1][a_c] = pa1;
            ulonglong2* d0 = (ulonglong2*)&Xd[nxt][x_r0][2 * x_c0];
            d0[0] = make_ulonglong2(dup2(px0.x), dup2(px0.y));
            d0[1] = make_ulonglong2(dup2(px0.z), dup2(px0.w));
            if (tid < 128) {
                ulonglong2* d1 = (ulonglong2*)&Xd[nxt][x_r1][2 * x_c1];
                d1[0] = make_ulonglong2(dup2(px1.x), dup2(px1.y));
                d1[1] = make_ulonglong2(dup2(px1.z), dup2(px1.w));
            }
            __syncthreads();
        }
    }

    // epilogue: unpack n-pairs, store rows
    #pragma unroll
    for (int p = 0; p < 4; ++p) {
        float vlo[6], vhi[6];
        #pragma unroll
        for (int j = 0; j < 6; ++j) {
            asm("mov.b64 {%0, %1}, %2;" : "=f"(vlo[j]), "=f"(vhi[j]) : "l"(c2[p][j]));
        }
        const int row = n0 + ty * 8 + 2 * p;
        float* d0 = gY + ((size_t)((b * Kk + k) * Nn + row)) * FT + tx * 6;
        float* d1 = d0 + FT;
        *(float2*)(d0)     = make_float2(vlo[0], vlo[1]);
        *(float2*)(d0 + 2) = make_float2(vlo[2], vlo[3]);
        *(float2*)(d0 + 4) = make_float2(vlo[4], vlo[5]);
        *(float2*)(d1)     = make_float2(vhi[0], vhi[1]);
        *(float2*)(d1 + 2) = make_float2(vhi[2], vhi[3]);
        *(float2*)(d1 + 4) = make_float2(vhi[4], vhi[5]);
    }
}

// ---------------------------------------------------------------------------
// Kernel 2 (fused epi): processes GRP n per block, 2 n per iteration.
// Per iteration: theta contraction+relu -> Sp; (1x3) conv + residual + relu
// (channel-pair packed, 8 t per thread); LN; store.
// Pre-LN buffer overlays the Sp buffer (register-carried through normalize).
// ---------------------------------------------------------------------------
#define SB_WT   0                         // [tap][ci][c] 3*64*64 = 12288
#define SB_TH   (SB_WT + 12288)           // 576  (k,f,o)
#define SB_WR   (SB_TH + 576)             // [f][c] 192
#define SB_BI   (SB_WR + 192)             // 64
#define SB_GM   (SB_BI + 64)              // 64
#define SB_BB   (SB_GM + 64)              // 64
#define SB_XS   (SB_BB + 64)              // [2][96]
#define SB_YK   (SB_XS + 192)             // [2][3][96]
#define SB_SP   (SB_YK + 576)             // [2][64][36]; PO overlay [2][64][33]
#define SB_MU   (SB_SP + 2*64*36)         // [2][32]
#define SB_RS   (SB_MU + 64)              // [2][32]
#define SB_FLOATS (SB_RS + 64)
#define SB_BYTES (SB_FLOATS * 4)
#define GRP 8

__global__ __launch_bounds__(256) void fused_epi_kernel(
    const float* __restrict__ x,
    const float* __restrict__ theta,
    const float* __restrict__ w_time, const float* __restrict__ b_time,
    const float* __restrict__ w_res,  const float* __restrict__ b_res,
    const float* __restrict__ gamma,  const float* __restrict__ beta,
    float* __restrict__ out)
{
    extern __shared__ float sm[];
    const int ng0 = blockIdx.x * GRP;
    const int b   = blockIdx.y;
    const int tid = threadIdx.x;

    // ---- persistent weights ----
    for (int i = tid; i < Ct * Cc * 3; i += 256) {
        int c   = i / (Cc * 3);
        int r   = i - c * (Cc * 3);
        int ci  = r / 3;
        int tap = r - ci * 3;
        sm[SB_WT + tap * (Cc * Ct) + ci * Ct + c] = w_time[i];
    }
    for (int i = tid; i < Kk * Ff * Cc; i += 256) sm[SB_TH + i] = theta[i];
    if (tid < Ct * Ff) {
        int c = tid / 3, f = tid - c * 3;
        sm[SB_WR + f * Ct + c] = w_res[tid];
    }
    if (tid < Ct) {
        sm[SB_BI + tid] = b_time[tid] + b_res[tid];
        sm[SB_GM + tid] = gamma[tid];
        sm[SB_BB + tid] = beta[tid];
    }
    __syncthreads();

    const int nh   = tid >> 7;           // which n of the pair
    const int ltid = tid & 127;
    // theta stage: c over 64, 2 t-halves of 16
    const int cA  = ltid >> 1;
    const int tA  = (ltid & 1) * 16;
    // conv stage: channel pair (32), 8 t per thread
    const int c2i = ltid >> 2;
    const int tB  = (ltid & 3) * 8;
    // LN stats: t (32), 4 partial lanes
    const int tS  = ltid >> 2;
    const int sS  = ltid & 3;

    for (int np = 0; np < GRP / 2; ++np) {
        const int n0 = ng0 + 2 * np;

        // ---- loads: x slices + Y slices for both n ----
        if (tid < 2 * FT) {
            int h = tid / FT, ft = tid - h * FT;
            sm[SB_XS + h * FT + ft] = x[((size_t)(b * Nn + n0 + h)) * FT + ft];
        }
        for (int i = tid; i < 2 * Kk * FT; i += 256) {
            int h = i / (Kk * FT);
            int r = i - h * (Kk * FT);
            int k = r / FT, ft = r - k * FT;
            sm[SB_YK + i] = gY[((size_t)((b * Kk + k) * Nn + n0 + h)) * FT + ft];
        }
        __syncthreads();

        // ---- theta contraction + relu -> Sp[nh][cA][1+t], 16 t per thread ----
        {
            float sacc[16];
            #pragma unroll
            for (int j = 0; j < 16; ++j) sacc[j] = 0.f;
            #pragma unroll
            for (int k = 0; k < Kk; ++k)
                #pragma unroll
                for (int f = 0; f < Ff; ++f) {
                    const float coef = sm[SB_TH + k * (Ff * Cc) + f * Cc + cA];
                    const float* yp = &sm[SB_YK + nh * (Kk * FT) + k * FT + f * Tt + tA];
                    #pragma unroll
                    for (int j = 0; j < 16; ++j) sacc[j] += coef * yp[j];
                }
            float* sp = &sm[SB_SP + nh * (64 * 36) + cA * 36];
            #pragma unroll
            for (int j = 0; j < 16; ++j)
                sp[tA + j + 1] = fmaxf(sacc[j], 0.f);
            if (tA == 0) sp[0] = 0.f; else sp[33] = 0.f;
        }
        __syncthreads();

        // ---- conv (1x3) + residual, channel-pair packed, 8 t ----
        float vlo[8], vhi[8];
        {
            unsigned long long acc2[8];
            #pragma unroll
            for (int j = 0; j < 8; ++j) acc2[j] = 0ULL;

            const float* spb = &sm[SB_SP + nh * (64 * 36)];
            #pragma unroll 4
            for (int ci = 0; ci < Cc; ++ci) {
                unsigned long long w0 = *(const unsigned long long*)
                    &sm[SB_WT + 0 * (Cc * Ct) + ci * Ct + 2 * c2i];
                unsigned long long w1 = *(const unsigned long long*)
                    &sm[SB_WT + 1 * (Cc * Ct) + ci * Ct + 2 * c2i];
                unsigned long long w2 = *(const unsigned long long*)
                    &sm[SB_WT + 2 * (Cc * Ct) + ci * Ct + 2 * c2i];

                const float* srow = spb + ci * 36 + tB;   // covers t-1 .. t+8
                float4 s0 = *(const float4*)(srow);
                float4 s1 = *(const float4*)(srow + 4);
                float2 s2 = *(const float2*)(srow + 8);
                unsigned long long d[10];
                d[0] = dup2(s0.x); d[1] = dup2(s0.y); d[2] = dup2(s0.z); d[3] = dup2(s0.w);
                d[4] = dup2(s1.x); d[5] = dup2(s1.y); d[6] = dup2(s1.z); d[7] = dup2(s1.w);
                d[8] = dup2(s2.x); d[9] = dup2(s2.y);
                #pragma unroll
                for (int j = 0; j < 8; ++j) {
                    asm("fma.rn.f32x2 %0, %1, %2, %0;" : "+l"(acc2[j]) : "l"(w0), "l"(d[j]));
                    asm("fma.rn.f32x2 %0, %1, %2, %0;" : "+l"(acc2[j]) : "l"(w1), "l"(d[j + 1]));
                    asm("fma.rn.f32x2 %0, %1, %2, %0;" : "+l"(acc2[j]) : "l"(w2), "l"(d[j + 2]));
                }
            }
            // residual 1x1
            #pragma unroll
            for (int f = 0; f < Ff; ++f) {
                unsigned long long wr = *(const unsigned long long*)
                    &sm[SB_WR + f * Ct + 2 * c2i];
                const float* xf = &sm[SB_XS + nh * FT + f * Tt + tB];
                #pragma unroll
                for (int j = 0; j < 8; ++j) {
                    unsigned long long xd = dup2(xf[j]);
                    asm("fma.rn.f32x2 %0, %1, %2, %0;" : "+l"(acc2[j]) : "l"(wr), "l"(xd));
                }
            }
            const float blo = sm[SB_BI + 2 * c2i];
            const float bhi = sm[SB_BI + 2 * c2i + 1];
            #pragma unroll
            for (int j = 0; j < 8; ++j) {
                float lo, hi;
                asm("mov.b64 {%0, %1}, %2;" : "=f"(lo), "=f"(hi) : "l"(acc2[j]));
                vlo[j] = fmaxf(lo + blo, 0.f);
                vhi[j] = fmaxf(hi + bhi, 0.f);
            }
        }
        __syncthreads();   // all Sp reads done -> safe to overlay PO

        // write pre-LN values into overlay [nh][c][33]
        {
            float* polo = &sm[SB_SP + nh * (64 * 36) + (2 * c2i) * 33];
            float* pohi = polo + 33;
            #pragma unroll
            for (int j = 0; j < 8; ++j) {
                polo[tB + j] = vlo[j];
                pohi[tB + j] = vhi[j];
            }
        }
        __syncthreads();

        // ---- LN stats over channel ----
        {
            const float* po = &sm[SB_SP + nh * (64 * 36)];
            float sum = 0.f, sq = 0.f;
            #pragma unroll
            for (int q = 0; q < 16; ++q) {
                float v = po[(sS * 16 + q) * 33 + tS];
                sum += v; sq += v * v;
            }
            sum += __shfl_xor_sync(0xffffffffu, sum, 1);
            sq  += __shfl_xor_sync(0xffffffffu, sq,  1);
            sum += __shfl_xor_sync(0xffffffffu, sum, 2);
            sq  += __shfl_xor_sync(0xffffffffu, sq,  2);
            if (sS == 0) {
                float m   = sum * (1.f / Ct);
                float var = sq * (1.f / Ct) - m * m;
                sm[SB_MU + nh * 32 + tS] = m;
                sm[SB_RS + nh * 32 + tS] = rsqrtf(var + 1e-5f);
            }
        }
        __syncthreads();

        // ---- normalize from registers + store ----
        {
            const int clo = 2 * c2i, chi = clo + 1;
            const float glo = sm[SB_GM + clo], bl = sm[SB_BB + clo];
            const float ghi = sm[SB_GM + chi], bh = sm[SB_BB + chi];
            float olo[8], ohi[8];
            #pragma unroll
            for (int j = 0; j < 8; ++j) {
                const int t = tB + j;
                const float mu = sm[SB_MU + nh * 32 + t];
                const float rs = sm[SB_RS + nh * 32 + t];
                olo[j] = (vlo[j] - mu) * rs * glo + bl;
                ohi[j] = (vhi[j] - mu) * rs * ghi + bh;
            }
            float* obase = out + ((size_t)(b * Nn + n0 + nh)) * Ct * Tt;
            *(float4*)(obase + clo * Tt + tB)     = make_float4(olo[0], olo[1], olo[2], olo[3]);
            *(float4*)(obase + clo * Tt + tB + 4) = make_float4(olo[4], olo[5], olo[6], olo[7]);
            *(float4*)(obase + chi * Tt + tB)     = make_float4(ohi[0], ohi[1], ohi[2], ohi[3]);
            *(float4*)(obase + chi * Tt + tB + 4) = make_float4(ohi[4], ohi[5], ohi[6], ohi[7]);
        }
        __syncthreads();   // protect Sp/YK/XS before next iteration
    }
}

// ---------------------------------------------------------------------------
extern "C" void kernel_launch(void* const* d_in, const int* in_sizes, int n_in,
                              void* d_out, int out_size)
{
    const float* x      = (const float*)d_in[0];
    const float* cheb   = (const float*)d_in[1];
    const float* theta  = (const float*)d_in[2];
    const float* w_time = (const float*)d_in[3];
    const float* b_time = (const float*)d_in[4];
    const float* w_res  = (const float*)d_in[5];
    const float* b_res  = (const float*)d_in[6];
    const float* gamma  = (const float*)d_in[7];
    const float* beta   = (const float*)d_in[8];
    float* out = (float*)d_out;

    cudaFuncSetAttribute(fused_epi_kernel,
                         cudaFuncAttributeMaxDynamicSharedMemorySize, SB_BYTES);

    gemm1_kernel<<<dim3(Nn / 128, Kk, Bb), 256>>>(cheb, x);
    fused_epi_kernel<<<dim3(Nn / GRP, Bb), 256, SB_BYTES>>>(
        x, theta, w_time, b_time, w_res, b_res, gamma, beta, out);
}

// round 6
// speedup vs baseline: 11.3973x; 1.3250x over previous
#include <cuda_runtime.h>
#include <cuda_bf16.h>
#include <cstdint>

#define Bb 32
#define Nn 1024
#define Ff 3
#define Tt 32
#define Kk 3
#define Cc 64
#define Ct 64
#define FT (Ff*Tt)   // 96

// Scratch
__device__ float gY[(size_t)Bb * Kk * Nn * FT];            // 37.7 MB
__device__ __nv_bfloat16 gAh[(size_t)Kk * Nn * Nn];        // cheb^T hi [k][n][m]
__device__ __nv_bfloat16 gAl[(size_t)Kk * Nn * Nn];        // cheb^T lo
__device__ __nv_bfloat16 gXh[(size_t)Bb * FT * Nn];        // x^T hi [b][ft][m]
__device__ __nv_bfloat16 gXl[(size_t)Bb * FT * Nn];        // x^T lo

__device__ __forceinline__ unsigned long long dup2(float v) {
    unsigned long long d;
    asm("mov.b64 %0, {%1, %1};" : "=l"(d) : "f"(v));
    return d;
}
__device__ __forceinline__ uint32_t s2u(const void* p) {
    uint32_t a;
    asm("{ .reg .u64 t; cvta.to.shared.u64 t, %1; cvt.u32.u64 %0, t; }" : "=r"(a) : "l"(p));
    return a;
}
#define SWZ(o) ((o) ^ (((o) >> 3) & 0x70))

// ---------------------------------------------------------------------------
// Transpose + bf16 hi/lo split
// ---------------------------------------------------------------------------
__global__ __launch_bounds__(256) void convert_cheb(const float* __restrict__ cheb)
{
    __shared__ float t[32][33];
    const int k = blockIdx.z, m0 = blockIdx.x * 32, n0 = blockIdx.y * 32;
    const int tx = threadIdx.x, ty = threadIdx.y;   // (32,8)
    #pragma unroll
    for (int j = 0; j < 4; ++j)
        t[ty + j * 8][tx] = cheb[((size_t)(k * Nn + m0 + ty + j * 8)) * Nn + n0 + tx];
    __syncthreads();
    #pragma unroll
    for (int j = 0; j < 4; ++j) {
        const int n = n0 + ty + j * 8, m = m0 + tx;
        float v = t[tx][ty + j * 8];
        __nv_bfloat16 h = __float2bfloat16(v);
        __nv_bfloat16 l = __float2bfloat16(v - __bfloat162float(h));
        gAh[((size_t)(k * Nn + n)) * Nn + m] = h;
        gAl[((size_t)(k * Nn + n)) * Nn + m] = l;
    }
}

__global__ __launch_bounds__(256) void convert_x(const float* __restrict__ x)
{
    __shared__ float t[32][33];
    const int b = blockIdx.z, m0 = blockIdx.x * 32, f0 = blockIdx.y * 32;
    const int tx = threadIdx.x, ty = threadIdx.y;
    #pragma unroll
    for (int j = 0; j < 4; ++j)
        t[ty + j * 8][tx] = x[((size_t)(b * Nn + m0 + ty + j * 8)) * FT + f0 + tx];
    __syncthreads();
    #pragma unroll
    for (int j = 0; j < 4; ++j) {
        const int ft = f0 + ty + j * 8, m = m0 + tx;
        float v = t[tx][ty + j * 8];
        __nv_bfloat16 h = __float2bfloat16(v);
        __nv_bfloat16 l = __float2bfloat16(v - __bfloat162float(h));
        gXh[((size_t)b * FT + ft) * Nn + m] = h;
        gXl[((size_t)b * FT + ft) * Nn + m] = l;
    }
}

// ---------------------------------------------------------------------------
// mma.sync bf16-split GEMM: Y[b,k,n,ft] = sum_m cheb[k,m,n]*x[b,m,ft]
// CTA: M=128 (n), N=96 (ft), KC=64 m-chunks, 16 chunks.
// 8 warps (4 m x 2 n), warp tile 32x48. 3 products: AhXh + AhXl + AlXh.
// ---------------------------------------------------------------------------
#define KC 64
#define ASZ (128 * KC * 2)
#define XSZ (96  * KC * 2)
#define SM_AH 0
#define SM_AL (SM_AH + ASZ)
#define SM_XH (SM_AL + ASZ)
#define SM_XL (SM_XH + XSZ)
#define GEMM_SMEM (SM_XL + XSZ)   // 57344

__device__ __forceinline__ void cp16(uint32_t dst, const void* src) {
    asm volatile("cp.async.cg.shared.global [%0], [%1], 16;" :: "r"(dst), "l"(src));
}
__device__ __forceinline__ void ldmx4(uint32_t* r, uint32_t addr) {
    asm volatile("ldmatrix.sync.aligned.m8n8.x4.shared.b16 {%0,%1,%2,%3}, [%4];"
                 : "=r"(r[0]), "=r"(r[1]), "=r"(r[2]), "=r"(r[3]) : "r"(addr));
}
__device__ __forceinline__ void mma16816(float* d, const uint32_t* a,
                                         uint32_t b0, uint32_t b1) {
    asm volatile(
        "mma.sync.aligned.m16n8k16.row.col.f32.bf16.bf16.f32 "
        "{%0,%1,%2,%3}, {%4,%5,%6,%7}, {%8,%9}, {%0,%1,%2,%3};"
        : "+f"(d[0]), "+f"(d[1]), "+f"(d[2]), "+f"(d[3])
        : "r"(a[0]), "r"(a[1]), "r"(a[2]), "r"(a[3]), "r"(b0), "r"(b1));
}

__global__ __launch_bounds__(256) void gemm_mma_kernel()
{
    extern __shared__ char smem[];
    const int n0 = blockIdx.x * 128;
    const int k  = blockIdx.y;
    const int b  = blockIdx.z;
    const int tid  = threadIdx.x;
    const int wid  = tid >> 5, lane = tid & 31;
    const int wm   = wid & 3;        // 4 m-warps (32 rows each)
    const int wn   = wid >> 2;       // 2 n-warps (48 cols each)
    const uint32_t smb = s2u(smem);

    const size_t aBase = ((size_t)k * Nn + n0) * Nn;
    const size_t xBase = (size_t)b * FT * Nn;

    float acc[2][6][4];
    #pragma unroll
    for (int i = 0; i < 2; ++i)
        #pragma unroll
        for (int j = 0; j < 6; ++j)
            #pragma unroll
            for (int q = 0; q < 4; ++q) acc[i][j][q] = 0.f;

    // ldmatrix lane geometry (shared across all frag loads)
    const int lrow = (lane & 7) + ((lane >> 3) & 1) * 8;   // row within 16-block
    const int lkb  = (lane >> 4) * 16;                     // k byte offset (0 or 16)

    const int NCH = Nn / KC;   // 16
    for (int c = 0; c < NCH; ++c) {
        // ---- cp.async loads (swizzled) ----
        const size_t mOff = (size_t)c * KC;
        for (int i = tid; i < 1024; i += 256) {
            const int row = i >> 3, seg = i & 7;
            const uint32_t so = SWZ(row * 128 + seg * 16);
            const size_t gi = aBase + (size_t)row * Nn + mOff + seg * 8;
            cp16(smb + SM_AH + so, gAh + gi);
            cp16(smb + SM_AL + so, gAl + gi);
        }
        for (int i = tid; i < 768; i += 256) {
            const int row = i >> 3, seg = i & 7;
            const uint32_t so = SWZ(row * 128 + seg * 16);
            const size_t gi = xBase + (size_t)row * Nn + mOff + seg * 8;
            cp16(smb + SM_XH + so, gXh + gi);
            cp16(smb + SM_XL + so, gXl + gi);
        }
        asm volatile("cp.async.commit_group;" ::: "memory");
        asm volatile("cp.async.wait_group 0;" ::: "memory");
        __syncthreads();

        // ---- 4 k-steps of mma ----
        #pragma unroll
        for (int ks = 0; ks < 4; ++ks) {
            const int kb = ks * 32 + lkb;   // byte offset of this lane's k segment

            uint32_t ah[2][4], al[2][4];
            #pragma unroll
            for (int mf = 0; mf < 2; ++mf) {
                const int r = wm * 32 + mf * 16 + lrow;
                const uint32_t off = SWZ(r * 128 + kb);
                ldmx4(ah[mf], smb + SM_AH + off);
                ldmx4(al[mf], smb + SM_AL + off);
            }
            uint32_t xh[3][4], xl[3][4];
            #pragma unroll
            for (int blk = 0; blk < 3; ++blk) {
                const int r = wn * 48 + blk * 16 + lrow;
                const uint32_t off = SWZ(r * 128 + kb);
                ldmx4(xh[blk], smb + SM_XH + off);
                ldmx4(xl[blk], smb + SM_XL + off);
            }

            #pragma unroll
            for (int mf = 0; mf < 2; ++mf)
                #pragma unroll
                for (int blk = 0; blk < 3; ++blk)
                    #pragma unroll
                    for (int sub = 0; sub < 2; ++sub) {
                        float* d = acc[mf][blk * 2 + sub];
                        mma16816(d, ah[mf], xh[blk][sub], xh[blk][sub + 2]);
                        mma16816(d, ah[mf], xl[blk][sub], xl[blk][sub + 2]);
                        mma16816(d, al[mf], xh[blk][sub], xh[blk][sub + 2]);
                    }
        }
        __syncthreads();
    }

    // ---- store fp32 Y ----
    const int qrow = lane >> 2;          // 0..7
    const int qcol = (lane & 3) * 2;     // 0,2,4,6
    #pragma unroll
    for (int mf = 0; mf < 2; ++mf) {
        #pragma unroll
        for (int nf = 0; nf < 6; ++nf) {
            const int nrow = n0 + wm * 32 + mf * 16 + qrow;
            const int col  = wn * 48 + nf * 8 + qcol;
            float* base = gY + ((size_t)((b * Kk + k) * Nn) + nrow) * FT + col;
            *(float2*)(base)          = make_float2(acc[mf][nf][0], acc[mf][nf][1]);
            *(float2*)(base + 8 * FT) = make_float2(acc[mf][nf][2], acc[mf][nf][3]);
        }
    }
}

// ---------------------------------------------------------------------------
// Fused epilogue (unchanged from round 3)
// ---------------------------------------------------------------------------
#define SB_WT   0
#define SB_TH   (SB_WT + 12288)
#define SB_WR   (SB_TH + 576)
#define SB_BI   (SB_WR + 192)
#define SB_GM   (SB_BI + 64)
#define SB_BB   (SB_GM + 64)
#define SB_XS   (SB_BB + 64)
#define SB_YK   (SB_XS + 192)
#define SB_SP   (SB_YK + 576)
#define SB_MU   (SB_SP + 2*64*36)
#define SB_RS   (SB_MU + 64)
#define SB_FLOATS (SB_RS + 64)
#define SB_BYTES (SB_FLOATS * 4)
#define GRP 8

__global__ __launch_bounds__(256) void fused_epi_kernel(
    const float* __restrict__ x,
    const float* __restrict__ theta,
    const float* __restrict__ w_time, const float* __restrict__ b_time,
    const float* __restrict__ w_res,  const float* __restrict__ b_res,
    const float* __restrict__ gamma,  const float* __restrict__ beta,
    float* __restrict__ out)
{
    extern __shared__ float sm[];
    const int ng0 = blockIdx.x * GRP;
    const int b   = blockIdx.y;
    const int tid = threadIdx.x;

    for (int i = tid; i < Ct * Cc * 3; i += 256) {
        int c   = i / (Cc * 3);
        int r   = i - c * (Cc * 3);
        int ci  = r / 3;
        int tap = r - ci * 3;
        sm[SB_WT + tap * (Cc * Ct) + ci * Ct + c] = w_time[i];
    }
    for (int i = tid; i < Kk * Ff * Cc; i += 256) sm[SB_TH + i] = theta[i];
    if (tid < Ct * Ff) {
        int c = tid / 3, f = tid - c * 3;
        sm[SB_WR + f * Ct + c] = w_res[tid];
    }
    if (tid < Ct) {
        sm[SB_BI + tid] = b_time[tid] + b_res[tid];
        sm[SB_GM + tid] = gamma[tid];
        sm[SB_BB + tid] = beta[tid];
    }
    __syncthreads();

    const int nh   = tid >> 7;
    const int ltid = tid & 127;
    const int cA  = ltid >> 1;
    const int tA  = (ltid & 1) * 16;
    const int c2i = ltid >> 2;
    const int tB  = (ltid & 3) * 8;
    const int tS  = ltid >> 2;
    const int sS  = ltid & 3;

    for (int np = 0; np < GRP / 2; ++np) {
        const int n0 = ng0 + 2 * np;

        if (tid < 2 * FT) {
            int h = tid / FT, ft = tid - h * FT;
            sm[SB_XS + h * FT + ft] = x[((size_t)(b * Nn + n0 + h)) * FT + ft];
        }
        for (int i = tid; i < 2 * Kk * FT; i += 256) {
            int h = i / (Kk * FT);
            int r = i - h * (Kk * FT);
            int k = r / FT, ft = r - k * FT;
            sm[SB_YK + i] = gY[((size_t)((b * Kk + k) * Nn + n0 + h)) * FT + ft];
        }
        __syncthreads();

        {
            float sacc[16];
            #pragma unroll
            for (int j = 0; j < 16; ++j) sacc[j] = 0.f;
            #pragma unroll
            for (int k = 0; k < Kk; ++k)
                #pragma unroll
                for (int f = 0; f < Ff; ++f) {
                    const float coef = sm[SB_TH + k * (Ff * Cc) + f * Cc + cA];
                    const float* yp = &sm[SB_YK + nh * (Kk * FT) + k * FT + f * Tt + tA];
                    #pragma unroll
                    for (int j = 0; j < 16; ++j) sacc[j] += coef * yp[j];
                }
            float* sp = &sm[SB_SP + nh * (64 * 36) + cA * 36];
            #pragma unroll
            for (int j = 0; j < 16; ++j)
                sp[tA + j + 1] = fmaxf(sacc[j], 0.f);
            if (tA == 0) sp[0] = 0.f; else sp[33] = 0.f;
        }
        __syncthreads();

        float vlo[8], vhi[8];
        {
            unsigned long long acc2[8];
            #pragma unroll
            for (int j = 0; j < 8; ++j) acc2[j] = 0ULL;

            const float* spb = &sm[SB_SP + nh * (64 * 36)];
            #pragma unroll 4
            for (int ci = 0; ci < Cc; ++ci) {
                unsigned long long w0 = *(const unsigned long long*)
                    &sm[SB_WT + 0 * (Cc * Ct) + ci * Ct + 2 * c2i];
                unsigned long long w1 = *(const unsigned long long*)
                    &sm[SB_WT + 1 * (Cc * Ct) + ci * Ct + 2 * c2i];
                unsigned long long w2 = *(const unsigned long long*)
                    &sm[SB_WT + 2 * (Cc * Ct) + ci * Ct + 2 * c2i];

                const float* srow = spb + ci * 36 + tB;
                float4 s0 = *(const float4*)(srow);
                float4 s1 = *(const float4*)(srow + 4);
                float2 s2 = *(const float2*)(srow + 8);
                unsigned long long d[10];
                d[0] = dup2(s0.x); d[1] = dup2(s0.y); d[2] = dup2(s0.z); d[3] = dup2(s0.w);
                d[4] = dup2(s1.x); d[5] = dup2(s1.y); d[6] = dup2(s1.z); d[7] = dup2(s1.w);
                d[8] = dup2(s2.x); d[9] = dup2(s2.y);
                #pragma unroll
                for (int j = 0; j < 8; ++j) {
                    asm("fma.rn.f32x2 %0, %1, %2, %0;" : "+l"(acc2[j]) : "l"(w0), "l"(d[j]));
                    asm("fma.rn.f32x2 %0, %1, %2, %0;" : "+l"(acc2[j]) : "l"(w1), "l"(d[j + 1]));
                    asm("fma.rn.f32x2 %0, %1, %2, %0;" : "+l"(acc2[j]) : "l"(w2), "l"(d[j + 2]));
                }
            }
            #pragma unroll
            for (int f = 0; f < Ff; ++f) {
                unsigned long long wr = *(const unsigned long long*)
                    &sm[SB_WR + f * Ct + 2 * c2i];
                const float* xf = &sm[SB_XS + nh * FT + f * Tt + tB];
                #pragma unroll
                for (int j = 0; j < 8; ++j) {
                    unsigned long long xd = dup2(xf[j]);
                    asm("fma.rn.f32x2 %0, %1, %2, %0;" : "+l"(acc2[j]) : "l"(wr), "l"(xd));
                }
            }
            const float blo = sm[SB_BI + 2 * c2i];
            const float bhi = sm[SB_BI + 2 * c2i + 1];
            #pragma unroll
            for (int j = 0; j < 8; ++j) {
                float lo, hi;
                asm("mov.b64 {%0, %1}, %2;" : "=f"(lo), "=f"(hi) : "l"(acc2[j]));
                vlo[j] = fmaxf(lo + blo, 0.f);
                vhi[j] = fmaxf(hi + bhi, 0.f);
            }
        }
        __syncthreads();

        {
            float* polo = &sm[SB_SP + nh * (64 * 36) + (2 * c2i) * 33];
            float* pohi = polo + 33;
            #pragma unroll
            for (int j = 0; j < 8; ++j) {
                polo[tB + j] = vlo[j];
                pohi[tB + j] = vhi[j];
            }
        }
        __syncthreads();

        {
            const float* po = &sm[SB_SP + nh * (64 * 36)];
            float sum = 0.f, sq = 0.f;
            #pragma unroll
            for (int q = 0; q < 16; ++q) {
                float v = po[(sS * 16 + q) * 33 + tS];
                sum += v; sq += v * v;
            }
            sum += __shfl_xor_sync(0xffffffffu, sum, 1);
            sq  += __shfl_xor_sync(0xffffffffu, sq,  1);
            sum += __shfl_xor_sync(0xffffffffu, sum, 2);
            sq  += __shfl_xor_sync(0xffffffffu, sq,  2);
            if (sS == 0) {
                float m   = sum * (1.f / Ct);
                float var = sq * (1.f / Ct) - m * m;
                sm[SB_MU + nh * 32 + tS] = m;
                sm[SB_RS + nh * 32 + tS] = rsqrtf(var + 1e-5f);
            }
        }
        __syncthreads();

        {
            const int clo = 2 * c2i, chi = clo + 1;
            const float glo = sm[SB_GM + clo], bl = sm[SB_BB + clo];
            const float ghi = sm[SB_GM + chi], bh = sm[SB_BB + chi];
            float olo[8], ohi[8];
            #pragma unroll
            for (int j = 0; j < 8; ++j) {
                const int t = tB + j;
                const float mu = sm[SB_MU + nh * 32 + t];
                const float rs = sm[SB_RS + nh * 32 + t];
                olo[j] = (vlo[j] - mu) * rs * glo + bl;
                ohi[j] = (vhi[j] - mu) * rs * ghi + bh;
            }
            float* obase = out + ((size_t)(b * Nn + n0 + nh)) * Ct * Tt;
            *(float4*)(obase + clo * Tt + tB)     = make_float4(olo[0], olo[1], olo[2], olo[3]);
            *(float4*)(obase + clo * Tt + tB + 4) = make_float4(olo[4], olo[5], olo[6], olo[7]);
            *(float4*)(obase + chi * Tt + tB)     = make_float4(ohi[0], ohi[1], ohi[2], ohi[3]);
            *(float4*)(obase + chi * Tt + tB + 4) = make_float4(ohi[4], ohi[5], ohi[6], ohi[7]);
        }
        __syncthreads();
    }
}

// ---------------------------------------------------------------------------
extern "C" void kernel_launch(void* const* d_in, const int* in_sizes, int n_in,
                              void* d_out, int out_size)
{
    const float* x      = (const float*)d_in[0];
    const float* cheb   = (const float*)d_in[1];
    const float* theta  = (const float*)d_in[2];
    const float* w_time = (const float*)d_in[3];
    const float* b_time = (const float*)d_in[4];
    const float* w_res  = (const float*)d_in[5];
    const float* b_res  = (const float*)d_in[6];
    const float* gamma  = (const float*)d_in[7];
    const float* beta   = (const float*)d_in[8];
    float* out = (float*)d_out;

    cudaFuncSetAttribute(fused_epi_kernel,
                         cudaFuncAttributeMaxDynamicSharedMemorySize, SB_BYTES);
    cudaFuncSetAttribute(gemm_mma_kernel,
                         cudaFuncAttributeMaxDynamicSharedMemorySize, GEMM_SMEM);

    convert_cheb<<<dim3(32, 32, 3), dim3(32, 8)>>>(cheb);
    convert_x<<<dim3(32, 3, 32), dim3(32, 8)>>>(x);
    gemm_mma_kernel<<<dim3(8, 3, 32), 256, GEMM_SMEM>>>();
    fused_epi_kernel<<<dim3(Nn / GRP, Bb), 256, SB_BYTES>>>(
        x, theta, w_time, b_time, w_res, b_res, gamma, beta, out);
}

// round 7
// speedup vs baseline: 14.8807x; 1.3056x over previous
#include <cuda_runtime.h>
#include <cuda_bf16.h>
#include <cstdint>

#define Bb 32
#define Nn 1024
#define Ff 3
#define Tt 32
#define Kk 3
#define Cc 64
#define Ct 64
#define FT (Ff*Tt)   // 96

// Scratch
__device__ float gY[(size_t)Bb * Kk * Nn * FT];            // 37.7 MB
__device__ __nv_bfloat16 gAh[(size_t)Kk * Nn * Nn];        // cheb^T hi [k][n][m]
__device__ __nv_bfloat16 gAl[(size_t)Kk * Nn * Nn];        // cheb^T lo
__device__ __nv_bfloat16 gXh[(size_t)Bb * FT * Nn];        // x^T hi [b][ft][m]
__device__ __nv_bfloat16 gXl[(size_t)Bb * FT * Nn];        // x^T lo
__device__ __nv_bfloat16 gWimH[64 * 200];                  // W im2col hi [c][200]
__device__ __nv_bfloat16 gWimL[64 * 200];                  // W im2col lo

__device__ __forceinline__ uint32_t s2u(const void* p) {
    uint32_t a;
    asm("{ .reg .u64 t; cvta.to.shared.u64 t, %1; cvt.u32.u64 %0, t; }" : "=r"(a) : "l"(p));
    return a;
}
#define SWZ(o) ((o) ^ (((o) >> 3) & 0x70))

__device__ __forceinline__ void cp16(uint32_t dst, const void* src) {
    asm volatile("cp.async.cg.shared.global [%0], [%1], 16;" :: "r"(dst), "l"(src));
}
__device__ __forceinline__ void ldmx4(uint32_t* r, uint32_t addr) {
    asm volatile("ldmatrix.sync.aligned.m8n8.x4.shared.b16 {%0,%1,%2,%3}, [%4];"
                 : "=r"(r[0]), "=r"(r[1]), "=r"(r[2]), "=r"(r[3]) : "r"(addr));
}
__device__ __forceinline__ void mma16816(float* d, const uint32_t* a,
                                         uint32_t b0, uint32_t b1) {
    asm volatile(
        "mma.sync.aligned.m16n8k16.row.col.f32.bf16.bf16.f32 "
        "{%0,%1,%2,%3}, {%4,%5,%6,%7}, {%8,%9}, {%0,%1,%2,%3};"
        : "+f"(d[0]), "+f"(d[1]), "+f"(d[2]), "+f"(d[3])
        : "r"(a[0]), "r"(a[1]), "r"(a[2]), "r"(a[3]), "r"(b0), "r"(b1));
}

// ---------------------------------------------------------------------------
// Prep: transpose + bf16 hi/lo split (cheb, x), W im2col split
// ---------------------------------------------------------------------------
__global__ __launch_bounds__(256) void convert_cheb(const float* __restrict__ cheb)
{
    __shared__ float t[32][33];
    const int k = blockIdx.z, m0 = blockIdx.x * 32, n0 = blockIdx.y * 32;
    const int tx = threadIdx.x, ty = threadIdx.y;
    #pragma unroll
    for (int j = 0; j < 4; ++j)
        t[ty + j * 8][tx] = cheb[((size_t)(k * Nn + m0 + ty + j * 8)) * Nn + n0 + tx];
    __syncthreads();
    #pragma unroll
    for (int j = 0; j < 4; ++j) {
        const int n = n0 + ty + j * 8, m = m0 + tx;
        float v = t[tx][ty + j * 8];
        __nv_bfloat16 h = __float2bfloat16(v);
        __nv_bfloat16 l = __float2bfloat16(v - __bfloat162float(h));
        gAh[((size_t)(k * Nn + n)) * Nn + m] = h;
        gAl[((size_t)(k * Nn + n)) * Nn + m] = l;
    }
}

__global__ __launch_bounds__(256) void convert_x(const float* __restrict__ x)
{
    __shared__ float t[32][33];
    const int b = blockIdx.z, m0 = blockIdx.x * 32, f0 = blockIdx.y * 32;
    const int tx = threadIdx.x, ty = threadIdx.y;
    #pragma unroll
    for (int j = 0; j < 4; ++j)
        t[ty + j * 8][tx] = x[((size_t)(b * Nn + m0 + ty + j * 8)) * FT + f0 + tx];
    __syncthreads();
    #pragma unroll
    for (int j = 0; j < 4; ++j) {
        const int ft = f0 + ty + j * 8, m = m0 + tx;
        float v = t[tx][ty + j * 8];
        __nv_bfloat16 h = __float2bfloat16(v);
        __nv_bfloat16 l = __float2bfloat16(v - __bfloat162float(h));
        gXh[((size_t)b * FT + ft) * Nn + m] = h;
        gXl[((size_t)b * FT + ft) * Nn + m] = l;
    }
}

// W im2col: Wim[c][tap*64+ci] = w_time[(c*64+ci)*3 + tap], rows padded to 200 elems
__global__ __launch_bounds__(256) void prep_wim(const float* __restrict__ w_time)
{
    int i = blockIdx.x * 256 + threadIdx.x;   // 64*192 = 12288
    if (i < 64 * 192) {
        int c = i / 192, r = i - c * 192;
        int tap = r >> 6, ci = r & 63;
        float v = w_time[(c * 64 + ci) * 3 + tap];
        __nv_bfloat16 h = __float2bfloat16(v);
        __nv_bfloat16 l = __float2bfloat16(v - __bfloat162float(h));
        gWimH[c * 200 + r] = h;
        gWimL[c * 200 + r] = l;
    }
    // init pad region (never read by ldmatrix, but cp.async copies it)
    if (i < 64 * 8) {
        int c = i >> 3, p = i & 7;
        gWimH[c * 200 + 192 + p] = __float2bfloat16(0.f);
        gWimL[c * 200 + 192 + p] = __float2bfloat16(0.f);
    }
}

// ---------------------------------------------------------------------------
// mma.sync bf16-split GEMM (unchanged from round 6)
// ---------------------------------------------------------------------------
#define KC 64
#define ASZ (128 * KC * 2)
#define XSZ (96  * KC * 2)
#define SM_AH 0
#define SM_AL (SM_AH + ASZ)
#define SM_XH (SM_AL + ASZ)
#define SM_XL (SM_XH + XSZ)
#define GEMM_SMEM (SM_XL + XSZ)   // 57344

__global__ __launch_bounds__(256) void gemm_mma_kernel()
{
    extern __shared__ char smem[];
    const int n0 = blockIdx.x * 128;
    const int k  = blockIdx.y;
    const int b  = blockIdx.z;
    const int tid  = threadIdx.x;
    const int wid  = tid >> 5, lane = tid & 31;
    const int wm   = wid & 3;
    const int wn   = wid >> 2;
    const uint32_t smb = s2u(smem);

    const size_t aBase = ((size_t)k * Nn + n0) * Nn;
    const size_t xBase = (size_t)b * FT * Nn;

    float acc[2][6][4];
    #pragma unroll
    for (int i = 0; i < 2; ++i)
        #pragma unroll
        for (int j = 0; j < 6; ++j)
            #pragma unroll
            for (int q = 0; q < 4; ++q) acc[i][j][q] = 0.f;

    const int lrow = (lane & 7) + ((lane >> 3) & 1) * 8;
    const int lkb  = (lane >> 4) * 16;

    const int NCH = Nn / KC;   // 16
    for (int c = 0; c < NCH; ++c) {
        const size_t mOff = (size_t)c * KC;
        for (int i = tid; i < 1024; i += 256) {
            const int row = i >> 3, seg = i & 7;
            const uint32_t so = SWZ(row * 128 + seg * 16);
            const size_t gi = aBase + (size_t)row * Nn + mOff + seg * 8;
            cp16(smb + SM_AH + so, gAh + gi);
            cp16(smb + SM_AL + so, gAl + gi);
        }
        for (int i = tid; i < 768; i += 256) {
            const int row = i >> 3, seg = i & 7;
            const uint32_t so = SWZ(row * 128 + seg * 16);
            const size_t gi = xBase + (size_t)row * Nn + mOff + seg * 8;
            cp16(smb + SM_XH + so, gXh + gi);
            cp16(smb + SM_XL + so, gXl + gi);
        }
        asm volatile("cp.async.commit_group;" ::: "memory");
        asm volatile("cp.async.wait_group 0;" ::: "memory");
        __syncthreads();

        #pragma unroll
        for (int ks = 0; ks < 4; ++ks) {
            const int kb = ks * 32 + lkb;
            uint32_t ah[2][4], al[2][4];
            #pragma unroll
            for (int mf = 0; mf < 2; ++mf) {
                const int r = wm * 32 + mf * 16 + lrow;
                const uint32_t off = SWZ(r * 128 + kb);
                ldmx4(ah[mf], smb + SM_AH + off);
                ldmx4(al[mf], smb + SM_AL + off);
            }
            uint32_t xh[3][4], xl[3][4];
            #pragma unroll
            for (int blk = 0; blk < 3; ++blk) {
                const int r = wn * 48 + blk * 16 + lrow;
                const uint32_t off = SWZ(r * 128 + kb);
                ldmx4(xh[blk], smb + SM_XH + off);
                ldmx4(xl[blk], smb + SM_XL + off);
            }
            #pragma unroll
            for (int mf = 0; mf < 2; ++mf)
                #pragma unroll
                for (int blk = 0; blk < 3; ++blk)
                    #pragma unroll
                    for (int sub = 0; sub < 2; ++sub) {
                        float* d = acc[mf][blk * 2 + sub];
                        mma16816(d, ah[mf], xh[blk][sub], xh[blk][sub + 2]);
                        mma16816(d, ah[mf], xl[blk][sub], xl[blk][sub + 2]);
                        mma16816(d, al[mf], xh[blk][sub], xh[blk][sub + 2]);
                    }
        }
        __syncthreads();
    }

    const int qrow = lane >> 2;
    const int qcol = (lane & 3) * 2;
    #pragma unroll
    for (int mf = 0; mf < 2; ++mf) {
        #pragma unroll
        for (int nf = 0; nf < 6; ++nf) {
            const int nrow = n0 + wm * 32 + mf * 16 + qrow;
            const int col  = wn * 48 + nf * 8 + qcol;
            float* base = gY + ((size_t)((b * Kk + k) * Nn) + nrow) * FT + col;
            *(float2*)(base)          = make_float2(acc[mf][nf][0], acc[mf][nf][1]);
            *(float2*)(base + 8 * FT) = make_float2(acc[mf][nf][2], acc[mf][nf][3]);
        }
    }
}

// ---------------------------------------------------------------------------
// Fused epilogue with tensor-core conv.
// Per iter (2 n): theta(fp32)+relu -> split hi/lo -> im2col Scol scatter;
// conv GEMM M=64(c) x N=64(2n*32t) x K=192 via mma.sync (3 split products);
// residual+bias+relu+LN scalar; store.
// smem rows (W and Scol): 400-byte stride (192 bf16 data + pad).
// ---------------------------------------------------------------------------
#define RSB  400
#define EWIH 0
#define EWIL 25600
#define ESCH 51200
#define ESCL 76800
#define EPO  51200            // fp32 [64][66] overlay on ESCH
#define EXS  102400           // 2*96 f32
#define EYK  103168           // 2*3*96 f32
#define ETH  105472           // 576 f32
#define EWR  107776           // [f][c] 192 f32
#define EBI  108544           // 64 f32
#define EGM  108800
#define EBB  109056
#define EMU  109312           // 2*32 f32
#define ERS  109568           // 2*32 f32
#define ESMEM 109824
#define GRP 8

__global__ __launch_bounds__(256) void fused_epi_tc(
    const float* __restrict__ x,
    const float* __restrict__ theta,
    const float* __restrict__ w_res,
    const float* __restrict__ b_time, const float* __restrict__ b_res,
    const float* __restrict__ gamma,  const float* __restrict__ beta,
    float* __restrict__ out)
{
    extern __shared__ char smem[];
    float* smf = (float*)smem;
    const uint32_t smb = s2u(smem);
    const int ng0 = blockIdx.x * GRP;
    const int b   = blockIdx.y;
    const int tid = threadIdx.x;
    const int wid = tid >> 5, lane = tid & 31;
    const int wm  = wid & 3, wn = wid >> 2;
    const int lrow = (lane & 7) + ((lane >> 3) & 1) * 8;
    const int lkb  = (lane >> 4) * 16;
    const int qrow = lane >> 2, qcol = (lane & 3) * 2;

    // ---- persistent: W im2col via cp.async, scalars ----
    for (int i = tid; i < 1600; i += 256) {
        cp16(smb + EWIH + i * 16, (const char*)gWimH + i * 16);
        cp16(smb + EWIL + i * 16, (const char*)gWimL + i * 16);
    }
    asm volatile("cp.async.commit_group;" ::: "memory");
    for (int i = tid; i < 576; i += 256) smf[ETH/4 + i] = theta[i];
    if (tid < 192) { int c = tid / 3, f = tid - c * 3; smf[EWR/4 + f * 64 + c] = w_res[tid]; }
    if (tid < 64) {
        smf[EBI/4 + tid] = b_time[tid] + b_res[tid];
        smf[EGM/4 + tid] = gamma[tid];
        smf[EBB/4 + tid] = beta[tid];
    }
    asm volatile("cp.async.wait_group 0;" ::: "memory");
    __syncthreads();

    const int nh   = tid >> 7;
    const int ltid = tid & 127;
    const int cA   = ltid >> 1;
    const int tA   = (ltid & 1) * 16;
    const int c2i  = ltid >> 2;
    const int tB   = (ltid & 3) * 8;
    const int tS   = ltid >> 2;
    const int sS   = ltid & 3;

    for (int np = 0; np < GRP / 2; ++np) {
        const int n0 = ng0 + 2 * np;

        // ---- per-iter loads ----
        if (tid < 2 * FT) {
            int h = tid / FT, ft = tid - h * FT;
            smf[EXS/4 + h * FT + ft] = x[((size_t)(b * Nn + n0 + h)) * FT + ft];
        }
        for (int i = tid; i < 2 * Kk * FT; i += 256) {
            int h = i / (Kk * FT), r = i - h * (Kk * FT);
            int k = r / FT, ft = r - k * FT;
            smf[EYK/4 + i] = gY[((size_t)((b * Kk + k) * Nn + n0 + h)) * FT + ft];
        }
        // zero im2col boundary slots: row t=0 cols[0,64) (tap0), row t=31 cols[128,192) (tap2)
        {
            const int which = (tid >> 6) & 1, ci = tid & 63, nz = tid >> 7;
            const int row = nz * 32 + (which ? 31 : 0);
            const int col = which ? (128 + ci) : ci;
            *(__nv_bfloat16*)(smem + ESCH + row * RSB + col * 2) = __float2bfloat16(0.f);
            *(__nv_bfloat16*)(smem + ESCL + row * RSB + col * 2) = __float2bfloat16(0.f);
        }
        __syncthreads();

        // ---- theta + relu + hi/lo split + im2col scatter ----
        {
            float sacc[16];
            #pragma unroll
            for (int j = 0; j < 16; ++j) sacc[j] = 0.f;
            #pragma unroll
            for (int k = 0; k < Kk; ++k)
                #pragma unroll
                for (int f = 0; f < Ff; ++f) {
                    const float coef = smf[ETH/4 + k * (Ff * Cc) + f * Cc + cA];
                    const float* yp = &smf[EYK/4 + nh * (Kk * FT) + k * FT + f * Tt + tA];
                    #pragma unroll
                    for (int j = 0; j < 16; ++j) sacc[j] += coef * yp[j];
                }
            const int rbase = nh * 32;
            #pragma unroll
            for (int j = 0; j < 16; ++j) {
                const int u = tA + j;
                const float v = fmaxf(sacc[j], 0.f);
                const __nv_bfloat16 h = __float2bfloat16(v);
                const __nv_bfloat16 l = __float2bfloat16(v - __bfloat162float(h));
                // tap 0 -> row u+1, col cA;  tap 1 -> row u, col 64+cA;  tap 2 -> row u-1, col 128+cA
                if (u + 1 < 32) {
                    const int off = (rbase + u + 1) * RSB + cA * 2;
                    *(__nv_bfloat16*)(smem + ESCH + off) = h;
                    *(__nv_bfloat16*)(smem + ESCL + off) = l;
                }
                {
                    const int off = (rbase + u) * RSB + (64 + cA) * 2;
                    *(__nv_bfloat16*)(smem + ESCH + off) = h;
                    *(__nv_bfloat16*)(smem + ESCL + off) = l;
                }
                if (u >= 1) {
                    const int off = (rbase + u - 1) * RSB + (128 + cA) * 2;
                    *(__nv_bfloat16*)(smem + ESCH + off) = h;
                    *(__nv_bfloat16*)(smem + ESCL + off) = l;
                }
            }
        }
        __syncthreads();

        // ---- conv GEMM: 8 warps, warp tile 16c x 32cols, K=192 ----
        float acc[4][4];
        #pragma unroll
        for (int i = 0; i < 4; ++i)
            #pragma unroll
            for (int q = 0; q < 4; ++q) acc[i][q] = 0.f;

        #pragma unroll
        for (int ks = 0; ks < 12; ++ks) {
            const int kb = ks * 32 + lkb;
            uint32_t ah[4], al[4], bh[2][4], bl[2][4];
            const uint32_t aoff = (wm * 16 + lrow) * RSB + kb;
            ldmx4(ah, smb + EWIH + aoff);
            ldmx4(al, smb + EWIL + aoff);
            #pragma unroll
            for (int cb = 0; cb < 2; ++cb) {
                const uint32_t boff = (wn * 32 + cb * 16 + lrow) * RSB + kb;
                ldmx4(bh[cb], smb + ESCH + boff);
                ldmx4(bl[cb], smb + ESCL + boff);
            }
            #pragma unroll
            for (int cb = 0; cb < 2; ++cb)
                #pragma unroll
                for (int sub = 0; sub < 2; ++sub) {
                    float* d = acc[cb * 2 + sub];
                    mma16816(d, ah, bh[cb][sub], bh[cb][sub + 2]);
                    mma16816(d, ah, bl[cb][sub], bl[cb][sub + 2]);
                    mma16816(d, al, bh[cb][sub], bh[cb][sub + 2]);
                }
        }
        __syncthreads();   // all Scol reads done -> safe to overlay PO

        // ---- write conv result to po [c][66] ----
        {
            float* po = smf + EPO/4;
            #pragma unroll
            for (int nf = 0; nf < 4; ++nf) {
                const int col = wn * 32 + nf * 8 + qcol;
                *(float2*)&po[(wm * 16 + qrow) * 66 + col]     = make_float2(acc[nf][0], acc[nf][1]);
                *(float2*)&po[(wm * 16 + qrow + 8) * 66 + col] = make_float2(acc[nf][2], acc[nf][3]);
            }
        }
        __syncthreads();

        // ---- residual + bias + relu (in place, keep regs) ----
        float vlo[8], vhi[8];
        {
            float* po = smf + EPO/4;
            const int clo = 2 * c2i, chi = clo + 1;
            const float wl0 = smf[EWR/4 + 0 * 64 + clo], wl1 = smf[EWR/4 + 1 * 64 + clo],
                        wl2 = smf[EWR/4 + 2 * 64 + clo];
            const float wh0 = smf[EWR/4 + 0 * 64 + chi], wh1 = smf[EWR/4 + 1 * 64 + chi],
                        wh2 = smf[EWR/4 + 2 * 64 + chi];
            const float blo = smf[EBI/4 + clo], bhi = smf[EBI/4 + chi];
            const float* xs = &smf[EXS/4 + nh * FT];
            #pragma unroll
            for (int j = 0; j < 8; ++j) {
                const int t = tB + j, col = nh * 32 + t;
                const float x0 = xs[t], x1 = xs[32 + t], x2 = xs[64 + t];
                vlo[j] = fmaxf(po[clo * 66 + col] + blo + wl0 * x0 + wl1 * x1 + wl2 * x2, 0.f);
                vhi[j] = fmaxf(po[chi * 66 + col] + bhi + wh0 * x0 + wh1 * x1 + wh2 * x2, 0.f);
                po[clo * 66 + col] = vlo[j];
                po[chi * 66 + col] = vhi[j];
            }
        }
        __syncthreads();

        // ---- LN stats over channel ----
        {
            const float* po = smf + EPO/4;
            float sum = 0.f, sq = 0.f;
            #pragma unroll
            for (int q = 0; q < 16; ++q) {
                const float v = po[(sS * 16 + q) * 66 + nh * 32 + tS];
                sum += v; sq += v * v;
            }
            sum += __shfl_xor_sync(0xffffffffu, sum, 1);
            sq  += __shfl_xor_sync(0xffffffffu, sq,  1);
            sum += __shfl_xor_sync(0xffffffffu, sum, 2);
            sq  += __shfl_xor_sync(0xffffffffu, sq,  2);
            if (sS == 0) {
                const float m = sum * (1.f / Ct);
                const float var = sq * (1.f / Ct) - m * m;
                smf[EMU/4 + nh * 32 + tS] = m;
                smf[ERS/4 + nh * 32 + tS] = rsqrtf(var + 1e-5f);
            }
        }
        __syncthreads();

        // ---- normalize from regs + store ----
        {
            const int clo = 2 * c2i, chi = clo + 1;
            const float glo = smf[EGM/4 + clo], bl = smf[EBB/4 + clo];
            const float ghi = smf[EGM/4 + chi], bh = smf[EBB/4 + chi];
            float olo[8], ohi[8];
            #pragma unroll
            for (int j = 0; j < 8; ++j) {
                const int t = tB + j;
                const float mu = smf[EMU/4 + nh * 32 + t];
                const float rs = smf[ERS/4 + nh * 32 + t];
                olo[j] = (vlo[j] - mu) * rs * glo + bl;
                ohi[j] = (vhi[j] - mu) * rs * ghi + bh;
            }
            float* obase = out + ((size_t)(b * Nn + n0 + nh)) * Ct * Tt;
            *(float4*)(obase + clo * Tt + tB)     = make_float4(olo[0], olo[1], olo[2], olo[3]);
            *(float4*)(obase + clo * Tt + tB + 4) = make_float4(olo[4], olo[5], olo[6], olo[7]);
            *(float4*)(obase + chi * Tt + tB)     = make_float4(ohi[0], ohi[1], ohi[2], ohi[3]);
            *(float4*)(obase + chi * Tt + tB + 4) = make_float4(ohi[4], ohi[5], ohi[6], ohi[7]);
        }
        __syncthreads();
    }
}

// ---------------------------------------------------------------------------
extern "C" void kernel_launch(void* const* d_in, const int* in_sizes, int n_in,
                              void* d_out, int out_size)
{
    const float* x      = (const float*)d_in[0];
    const float* cheb   = (const float*)d_in[1];
    const float* theta  = (const float*)d_in[2];
    const float* w_time = (const float*)d_in[3];
    const float* b_time = (const float*)d_in[4];
    const float* w_res  = (const float*)d_in[5];
    const float* b_res  = (const float*)d_in[6];
    const float* gamma  = (const float*)d_in[7];
    const float* beta   = (const float*)d_in[8];
    float* out = (float*)d_out;

    cudaFuncSetAttribute(gemm_mma_kernel,
                         cudaFuncAttributeMaxDynamicSharedMemorySize, GEMM_SMEM);
    cudaFuncSetAttribute(fused_epi_tc,
                         cudaFuncAttributeMaxDynamicSharedMemorySize, ESMEM);

    prep_wim<<<48, 256>>>(w_time);
    convert_cheb<<<dim3(32, 32, 3), dim3(32, 8)>>>(cheb);
    convert_x<<<dim3(32, 3, 32), dim3(32, 8)>>>(x);
    gemm_mma_kernel<<<dim3(8, 3, 32), 256, GEMM_SMEM>>>();
    fused_epi_tc<<<dim3(Nn / GRP, Bb), 256, ESMEM>>>(
        x, theta, w_res, b_time, b_res, gamma, beta, out);
}